// round 14
// baseline (speedup 1.0000x reference)
#include <cuda_runtime.h>
#include <cuda_bf16.h>
#include <cstdint>

#define T_STEPS 512
#define BATCH   64
#define NIN     1024
#define HDIM    1024
#define G4      4096      // 4*H
#define GRID_R  128       // persistent blocks (1 per SM, <=148 -> co-resident)
#define THR_R   128       // 4 warps, full K-split (zero redundant smem reads)
#define HPB     8         // h-columns per block (8*4 gates = 32 gate cols)
#define KC      128       // y k-chunk
#define YS_STRIDE 132     // padded row stride for y smem
#define STAGE_P 2048      // stage stride per warp (floats)

// -------- scratch (device globals: allocation-free rule) --------
// zx permuted: [t][blk][b*32 + col]  (2048 floats per (t,blk))
__device__ float    g_zx[134217728];          // 512 MB
__device__ float    g_xr[33554432];           // tf32-rounded X (128 MB)
__device__ float    g_wxr[4194304];           // tf32-rounded Wx (16 MB)
__device__ float    g_ybuf[2][BATCH * HDIM];  // double-buffered y state (tf32-rounded)
__device__ unsigned g_bar1[256];              // 8 level-1 counters, 128B apart
__device__ unsigned g_bar_top;                // level-2 counter (8 arrivals/step)

// ---------------- small helpers ----------------
__device__ __forceinline__ void cp16(unsigned saddr, const void* gptr) {
    asm volatile("cp.async.cg.shared.global [%0], [%1], 16;\n" :: "r"(saddr), "l"(gptr));
}
__device__ __forceinline__ void cp_commit() { asm volatile("cp.async.commit_group;\n"); }
__device__ __forceinline__ void cp_wait0()  { asm volatile("cp.async.wait_group 0;\n" ::: "memory"); }

__device__ __forceinline__ uint32_t tf32b(float x) {
    uint32_t u; asm("cvt.rna.tf32.f32 %0, %1;" : "=r"(u) : "f"(x)); return u;
}
__device__ __forceinline__ float tf32r(float x) { return __uint_as_float(tf32b(x)); }

__device__ __forceinline__ float fast_sig(float x) {
    float e; asm("ex2.approx.f32 %0, %1;" : "=f"(e) : "f"(-1.4426950408889634f * x));
    float r; asm("rcp.approx.f32 %0, %1;" : "=f"(r) : "f"(1.0f + e));
    return r;
}
__device__ __forceinline__ float fast_tanh(float x) {
    return fmaf(2.0f, fast_sig(2.0f * x), -1.0f);
}

__device__ __forceinline__ void mma_tf32(float* d, const uint32_t* a, const uint32_t* b) {
    asm volatile(
        "mma.sync.aligned.m16n8k8.row.col.f32.tf32.tf32.f32 "
        "{%0,%1,%2,%3}, {%4,%5,%6,%7}, {%8,%9}, {%0,%1,%2,%3};"
        : "+f"(d[0]), "+f"(d[1]), "+f"(d[2]), "+f"(d[3])
        : "r"(a[0]), "r"(a[1]), "r"(a[2]), "r"(a[3]), "r"(b[0]), "r"(b[1]));
}
__device__ __forceinline__ void ldsm4(uint32_t* r, const float* p) {
    uint32_t sa = (uint32_t)__cvta_generic_to_shared(p);
    asm volatile("ldmatrix.sync.aligned.m8n8.x4.shared.b16 {%0,%1,%2,%3}, [%4];"
                 : "=r"(r[0]), "=r"(r[1]), "=r"(r[2]), "=r"(r[3]) : "r"(sa));
}

// ================= Kernel 0: prep (bar reset + tf32 pre-round) =================
__global__ __launch_bounds__(256) void prep_kernel(
    const float* __restrict__ X, const float* __restrict__ W,
    const float* __restrict__ y0)
{
    size_t tid = (size_t)blockIdx.x * blockDim.x + threadIdx.x;
    size_t nthr = (size_t)gridDim.x * blockDim.x;
    if (blockIdx.x == 0 && threadIdx.x < 256) g_bar1[threadIdx.x] = 0u;
    if (tid == 0) g_bar_top = 0u;

    for (size_t i = tid; i < 33554432 / 4; i += nthr) {
        float4 v = ((const float4*)X)[i];
        v.x = tf32r(v.x); v.y = tf32r(v.y); v.z = tf32r(v.z); v.w = tf32r(v.w);
        ((float4*)g_xr)[i] = v;
    }
    for (size_t i = tid; i < 4194304 / 4; i += nthr) {
        float4 v = ((const float4*)W)[i];   // Wx = rows [0,1024)
        v.x = tf32r(v.x); v.y = tf32r(v.y); v.z = tf32r(v.z); v.w = tf32r(v.w);
        ((float4*)g_wxr)[i] = v;
    }
    for (size_t i = tid; i < (BATCH * HDIM) / 4; i += nthr) {
        float4 v = ((const float4*)y0)[i];
        v.x = tf32r(v.x); v.y = tf32r(v.y); v.z = tf32r(v.z); v.w = tf32r(v.w);
        ((float4*)g_ybuf[1])[i] = v;
    }
}

// ================= Kernel 1: Zx = Xr @ Wxr + b (TF32 mma, cvt-free) =================
#define ZA_STRIDE 20
#define ZB_STRIDE 136    // 136&31=8 -> B-load bank = 8*tg+8*nt+g, bijective (132 was 2-way)

__global__ __launch_bounds__(256) void zx_gemm_kernel(const float* __restrict__ bias)
{
    __shared__ __align__(16) float As[2][128 * ZA_STRIDE];
    __shared__ __align__(16) float Bs[2][16 * ZB_STRIDE];

    const int bm = blockIdx.y * 128;
    const int bn = blockIdx.x * 128;
    const int tid = threadIdx.x;
    const int wid = tid >> 5, lane = tid & 31;
    const int wm = (wid & 1) * 64;
    const int wn = (wid >> 1) * 32;
    const int g = lane >> 2, tg = lane & 3;
    const int t4 = lane >> 3, lr = lane & 7;
    const int rowb = wm + 8 * (t4 & 1) + lr;
    const int kadd = 4 * (t4 >> 1);

    float acc[4][4][4];
#pragma unroll
    for (int a = 0; a < 4; a++)
#pragma unroll
        for (int b = 0; b < 4; b++)
#pragma unroll
            for (int i = 0; i < 4; i++) acc[a][b][i] = 0.0f;

    auto load_tiles = [&](int buf, int k0) {
#pragma unroll
        for (int h = 0; h < 2; h++) {
            int u = tid + h * 256;
            int row = u >> 2, q = u & 3;
            cp16((unsigned)__cvta_generic_to_shared(&As[buf][row * ZA_STRIDE + q * 4]),
                 g_xr + (size_t)(bm + row) * NIN + k0 + q * 4);
            int k = u >> 5, qq = u & 31;
            cp16((unsigned)__cvta_generic_to_shared(&Bs[buf][k * ZB_STRIDE + qq * 4]),
                 g_wxr + (size_t)(k0 + k) * G4 + bn + qq * 4);
        }
        cp_commit();
    };

    load_tiles(0, 0);

    for (int kb = 0; kb < NIN / 16; kb++) {
        const int cur = kb & 1;
        cp_wait0();
        __syncthreads();
        if (kb < NIN / 16 - 1) load_tiles(cur ^ 1, (kb + 1) * 16);

        const float* A_ = As[cur];
        const float* B_ = Bs[cur];
#pragma unroll
        for (int kt = 0; kt < 2; kt++) {
            uint32_t a[4][4];
#pragma unroll
            for (int mt = 0; mt < 4; mt++)
                ldsm4(a[mt], &A_[(rowb + mt * 16) * ZA_STRIDE + kt * 8 + kadd]);
            uint32_t b[4][2];
#pragma unroll
            for (int nt = 0; nt < 4; nt++) {
                b[nt][0] = __float_as_uint(B_[(kt * 8 + tg) * ZB_STRIDE + wn + nt * 8 + g]);
                b[nt][1] = __float_as_uint(B_[(kt * 8 + tg + 4) * ZB_STRIDE + wn + nt * 8 + g]);
            }
#pragma unroll
            for (int mt = 0; mt < 4; mt++)
#pragma unroll
                for (int nt = 0; nt < 4; nt++)
                    mma_tf32(acc[mt][nt], a[mt], b[nt]);
        }
        __syncthreads();
    }

    // epilogue: add bias, store PERMUTED: g_zx[(t*128+blk)*2048 + b*32 + col]
#pragma unroll
    for (int mt = 0; mt < 4; mt++) {
#pragma unroll
        for (int nt = 0; nt < 4; nt++) {
            int n = bn + wn + nt * 8 + 2 * tg;     // even global gate col
            float2 bb = *(const float2*)&bias[n];
            int m0 = bm + wm + mt * 16 + g;        // rows m0, m0+8 (same t)
            int tt = m0 >> 6;
            int blkL = (n & 1023) >> 3;
            int col = ((n >> 10) << 3) + (n & 7);
            size_t base = ((size_t)tt * GRID_R + blkL) * 2048 + (m0 & 63) * 32 + col;
            float2 v0 = make_float2(acc[mt][nt][0] + bb.x, acc[mt][nt][1] + bb.y);
            float2 v1 = make_float2(acc[mt][nt][2] + bb.x, acc[mt][nt][3] + bb.y);
            *(float2*)&g_zx[base] = v0;
            *(float2*)&g_zx[base + 8 * 32] = v1;
        }
    }
}

// ================= Kernel 2: persistent recurrence (TF32 mma, full K-split) =================
#define SM_YS 32768
#define SM_ZS (32768 + 2 * (BATCH * YS_STRIDE))
#define SM_CS (SM_ZS + BATCH * 32)
#define SMEM_FLOATS (SM_CS + BATCH * HPB)
#define SMEM_BYTES (SMEM_FLOATS * 4)

__device__ __forceinline__ void load_y_chunk(int tid, float* dst, const float* src) {
#pragma unroll
    for (int gq = 0; gq < 16; gq++) {
        int grp = tid + gq * THR_R;       // 0..2047
        int b = grp >> 5, q = grp & 31;
        unsigned sa = (unsigned)__cvta_generic_to_shared(dst + b * YS_STRIDE + q * 4);
        cp16(sa, src + b * HDIM + q * 4);
    }
    cp_commit();
}

__global__ __launch_bounds__(THR_R, 1) void lstm_kernel(
    const float* __restrict__ W,      // (2048, 4096); Wh = rows [1024, 2048)
    const float* __restrict__ c0,
    const float* __restrict__ Igate,  // (T, B)
    float* __restrict__ out)
{
    extern __shared__ float smem[];
    float* whs = smem;            // 32768 floats: fragment-layout tf32 Wh^T
    float* ys  = smem + SM_YS;    // double-buffered y chunks; reused as stage
    float* zs  = smem + SM_ZS;    // z tile [64][32] (zx preloaded, reduced acc added)
    float* cs  = smem + SM_CS;    // c state [64][8]

    const int tid = threadIdx.x;
    const int blk = blockIdx.x;
    const int w = tid >> 5, lane = tid & 31;   // warp w owns k-iters w*4..w*4+3 per chunk
    const int g = lane >> 2, tg = lane & 3;

    // ---- one-time: Wh^T fragment layout (tf32-rounded) ----
    const float* WhG = W + (size_t)NIN * G4;
    for (int idx = tid; idx < NIN * 32; idx += THR_R) {
        int i = idx & 3;
        int ln = (idx >> 2) & 31;
        int mt = (idx >> 7) & 1;
        int kt = idx >> 8;
        int gg = ln >> 2, tg2 = ln & 3;
        int k = 8 * kt + tg2 + 4 * (i >> 1);
        int gcol = (2 * mt + (i & 1)) * HDIM + blk * HPB + gg;
        whs[idx] = tf32r(WhG[(size_t)k * G4 + gcol]);
    }
    for (int p = tid; p < BATCH * HPB; p += THR_R)
        cs[p] = c0[(p >> 3) * HDIM + blk * HPB + (p & 7)];
    __syncthreads();

    float* Yout  = out;
    float* Cout  = out + (size_t)T_STEPS * BATCH * HDIM;
    float* cTout = Cout + (size_t)T_STEPS * BATCH * HDIM;

    // reducer constants (thread -> m = lane)
    const int r_m  = lane;
    const int r_g  = lane & 7;
    const int r_h  = (lane >> 3) & 1;
    const int r_mt = lane >> 4;
    const int r_swz = (r_h << 3) | (r_mt << 4);
    const int r_lbase = (4 * r_g) ^ r_swz;     // tg bits (0..1) disjoint, OR'd in later

    // barrier tree constants
    unsigned* lvl1 = &g_bar1[(blk >> 4) * 32];   // 8 counters, 128B apart
    const bool leader = ((blk & 15) == 0);

    // prefetch zx slice for t=0
    {
        const float* zsrc = g_zx + (size_t)blk * 2048;
#pragma unroll
        for (int q = 0; q < 4; q++) {
            int u = tid + q * THR_R;
            cp16((unsigned)__cvta_generic_to_shared(zs + u * 4), zsrc + u * 4);
        }
        cp_commit();
    }

    for (int t = 0; t < T_STEPS; t++) {
        const float* ysrc = g_ybuf[(t & 1) ^ 1];

        // prefetch y chunk 0 (zx(t) already in flight / arrived)
        load_y_chunk(tid, ys, ysrc);

        float acc[2][8][4];
#pragma unroll
        for (int a = 0; a < 2; a++)
#pragma unroll
            for (int b = 0; b < 8; b++)
#pragma unroll
                for (int i = 0; i < 4; i++) acc[a][b][i] = 0.0f;

        cp_wait0();            // zx(t) + y chunk 0
        __syncthreads();

        // ---- z^T += Wh^T @ y^T; warp w owns k-iters w*4..w*4+3 of each chunk ----
        for (int ch = 0; ch < HDIM / KC; ch++) {
            if (ch < HDIM / KC - 1)
                load_y_chunk(tid, ys + ((ch + 1) & 1) * (BATCH * YS_STRIDE),
                             ysrc + (ch + 1) * KC);

            const float* yb = ys + (ch & 1) * (BATCH * YS_STRIDE);
#pragma unroll
            for (int q = 0; q < 4; q++) {
                int ktl = w * 4 + q;
                int ktg = ch * 16 + ktl;
                const float4* wp = ((const float4*)whs) + (size_t)(ktg * 2) * 32 + lane;
                float4 A0 = wp[0];
                float4 A1 = wp[32];
                uint32_t a0[4] = {__float_as_uint(A0.x), __float_as_uint(A0.y),
                                  __float_as_uint(A0.z), __float_as_uint(A0.w)};
                uint32_t a1[4] = {__float_as_uint(A1.x), __float_as_uint(A1.y),
                                  __float_as_uint(A1.z), __float_as_uint(A1.w)};
                int krow = ktl * 8 + tg;
                uint32_t bf[8][2];
#pragma unroll
                for (int nt = 0; nt < 8; nt++) {
                    bf[nt][0] = __float_as_uint(yb[(8 * nt + g) * YS_STRIDE + krow]);
                    bf[nt][1] = __float_as_uint(yb[(8 * nt + g) * YS_STRIDE + krow + 4]);
                }
#pragma unroll
                for (int nt = 0; nt < 8; nt++) {
                    mma_tf32(acc[0][nt], a0, bf[nt]);
                    mma_tf32(acc[1][nt], a1, bf[nt]);
                }
            }
            if (ch < HDIM / KC - 1) cp_wait0();
            __syncthreads();
        }

        // ---- stage 4 partial z tiles (swizzled, conflict-free) ----
        float* stage = ys;   // idle now; 4 * 2048 floats
        {
            float* sp = stage + w * STAGE_P;
#pragma unroll
            for (int mt = 0; mt < 2; mt++)
#pragma unroll
                for (int nt = 0; nt < 8; nt++)
#pragma unroll
                    for (int i = 0; i < 4; i++) {
                        int e = mt * 32 + nt * 4 + i;
                        int sl = lane ^ ((((e >> 1) & 1) << 3) | ((e >> 5) << 4));
                        sp[e * 32 + sl] = acc[mt][nt][i];
                    }
        }
        __syncthreads();

        // ---- reduce: thread handles m = lane, batches 16w..16w+15 ----
#pragma unroll
        for (int bb = 0; bb < 16; bb++) {
            int b = 16 * w + bb;
            int nt = b >> 3, tg2 = (b >> 1) & 3, j = b & 1;
            int e = r_mt * 32 + nt * 4 + 2 * r_h + j;
            int slot = e * 32 + (r_lbase | tg2);
            float s = stage[slot] + stage[STAGE_P + slot] +
                      stage[2 * STAGE_P + slot] + stage[3 * STAGE_P + slot];
            zs[b * 32 + r_m] += s;
        }
        __syncthreads();

        // ---- elementwise LSTM cell: 512 (b,jj) pairs, 4 per thread ----
        float* ywr = g_ybuf[t & 1];
        float yv[4], cv[4];
#pragma unroll
        for (int q = 0; q < 4; q++) {
            int p = tid + q * THR_R;
            int b = p >> 3, jj = p & 7;
            float z0 = zs[b * 32 + jj];
            float z1 = zs[b * 32 + 8 + jj];
            float z2 = zs[b * 32 + 16 + jj];
            float z3 = zs[b * 32 + 24 + jj];
            float ci = fast_tanh(z0);
            float ig = fast_sig(z1);
            float fg = fast_sig(z2);
            float og = fast_sig(z3);
            float cprev = cs[p];
            float c = fmaf(ci, ig, cprev * fg);
            float y = fast_tanh(c) * og;
            float m = Igate[t * BATCH + b];
            c = m * c + (1.0f - m) * cprev;
            y = m * y;
            cs[p] = c;
            yv[q] = y; cv[q] = c;
            ywr[b * HDIM + blk * HPB + jj] = tf32r(y);  // next-step mma input
        }

        // ---- barrier arrive: level-1 (8 parallel counters of 16 arrivals) ----
        __threadfence();
        __syncthreads();
        if (tid == 0) atomicAdd(lvl1, 1u);

        // prefetch next step's zx into zs during barrier window (zs reads done)
        if (t + 1 < T_STEPS) {
            const float* zsrc = g_zx + ((size_t)(t + 1) * GRID_R + blk) * 2048;
#pragma unroll
            for (int q = 0; q < 4; q++) {
                int u = tid + q * THR_R;
                cp16((unsigned)__cvta_generic_to_shared(zs + u * 4), zsrc + u * 4);
            }
            cp_commit();
        }

        // output stores hidden between arrive and wait (off critical path)
#pragma unroll
        for (int q = 0; q < 4; q++) {
            int p = tid + q * THR_R;
            int b = p >> 3, jj = p & 7;
            size_t row = (size_t)t * BATCH + b;
            int hcol = blk * HPB + jj;
            Yout[row * HDIM + hcol] = yv[q];
            Cout[row * HDIM + hcol] = cv[q];
        }

        // ---- barrier wait: leaders promote level-1 -> top; all poll top ----
        if (tid == 0) {
            if (leader) {
                unsigned t1 = 16u * (unsigned)(t + 1);
                volatile unsigned* v1 = lvl1;
                while (*v1 < t1) { }
                atomicAdd(&g_bar_top, 1u);
            }
            unsigned tt = 8u * (unsigned)(t + 1);
            volatile unsigned* vt = &g_bar_top;
            while (*vt < tt) { }
            __threadfence();
        }
        __syncthreads();
    }

    // final cell state
#pragma unroll
    for (int q = 0; q < 4; q++) {
        int p = tid + q * THR_R;
        cTout[(p >> 3) * HDIM + blk * HPB + (p & 7)] = cs[p];
    }
}

// ================= host =================
extern "C" void kernel_launch(void* const* d_in, const int* in_sizes, int n_in,
                              void* d_out, int out_size)
{
    (void)in_sizes; (void)n_in; (void)out_size;
    const float* X    = (const float*)d_in[0];
    const float* W    = (const float*)d_in[1];
    const float* bias = (const float*)d_in[2];
    const float* y0   = (const float*)d_in[3];
    const float* c0   = (const float*)d_in[4];
    const float* I    = (const float*)d_in[5];
    float* out = (float*)d_out;

    cudaFuncSetAttribute(lstm_kernel,
                         cudaFuncAttributeMaxDynamicSharedMemorySize, SMEM_BYTES);

    prep_kernel<<<512, 256>>>(X, W, y0);

    dim3 g1(G4 / 128, (T_STEPS * BATCH) / 128);
    zx_gemm_kernel<<<g1, 256>>>(bias);

    lstm_kernel<<<GRID_R, THR_R, SMEM_BYTES>>>(W, c0, I, out);
}

// round 15
// speedup vs baseline: 1.0499x; 1.0499x over previous
#include <cuda_runtime.h>
#include <cuda_bf16.h>
#include <cstdint>

#define T_STEPS 512
#define BATCH   64
#define NIN     1024
#define HDIM    1024
#define G4      4096      // 4*H
#define GRID_R  128       // persistent blocks (1 per SM, <=148 -> co-resident)
#define THR_R   128       // 4 warps, full K-split (zero redundant smem reads)
#define HPB     8         // h-columns per block (8*4 gates = 32 gate cols)
#define KC      128       // y k-chunk
#define YS_STRIDE 132     // padded row stride for y smem
#define STAGE_P 2048      // stage stride per warp (floats)

// -------- scratch (device globals: allocation-free rule) --------
// zx permuted: [t][blk][b*32 + col]  (2048 floats per (t,blk))
__device__ float    g_zx[134217728];          // 512 MB
__device__ float    g_xr[33554432];           // tf32-rounded X (128 MB)
__device__ float    g_wxr[4194304];           // tf32-rounded Wx (16 MB)
__device__ float    g_ybuf[2][BATCH * HDIM];  // double-buffered y state (tf32-rounded)
__device__ unsigned g_bar;                    // single atomic barrier counter (flat, proven)

// ---------------- small helpers ----------------
__device__ __forceinline__ void cp16(unsigned saddr, const void* gptr) {
    asm volatile("cp.async.cg.shared.global [%0], [%1], 16;\n" :: "r"(saddr), "l"(gptr));
}
__device__ __forceinline__ void cp_commit() { asm volatile("cp.async.commit_group;\n"); }
__device__ __forceinline__ void cp_wait0()  { asm volatile("cp.async.wait_group 0;\n" ::: "memory"); }

__device__ __forceinline__ uint32_t tf32b(float x) {
    uint32_t u; asm("cvt.rna.tf32.f32 %0, %1;" : "=r"(u) : "f"(x)); return u;
}
__device__ __forceinline__ float tf32r(float x) { return __uint_as_float(tf32b(x)); }

__device__ __forceinline__ float fast_sig(float x) {
    float e; asm("ex2.approx.f32 %0, %1;" : "=f"(e) : "f"(-1.4426950408889634f * x));
    float r; asm("rcp.approx.f32 %0, %1;" : "=f"(r) : "f"(1.0f + e));
    return r;
}
__device__ __forceinline__ float fast_tanh(float x) {
    return fmaf(2.0f, fast_sig(2.0f * x), -1.0f);
}

__device__ __forceinline__ void mma_tf32(float* d, const uint32_t* a, const uint32_t* b) {
    asm volatile(
        "mma.sync.aligned.m16n8k8.row.col.f32.tf32.tf32.f32 "
        "{%0,%1,%2,%3}, {%4,%5,%6,%7}, {%8,%9}, {%0,%1,%2,%3};"
        : "+f"(d[0]), "+f"(d[1]), "+f"(d[2]), "+f"(d[3])
        : "r"(a[0]), "r"(a[1]), "r"(a[2]), "r"(a[3]), "r"(b[0]), "r"(b[1]));
}
__device__ __forceinline__ void ldsm4(uint32_t* r, const float* p) {
    uint32_t sa = (uint32_t)__cvta_generic_to_shared(p);
    asm volatile("ldmatrix.sync.aligned.m8n8.x4.shared.b16 {%0,%1,%2,%3}, [%4];"
                 : "=r"(r[0]), "=r"(r[1]), "=r"(r[2]), "=r"(r[3]) : "r"(sa));
}

// ================= Kernel 0: prep (bar reset + tf32 pre-round) =================
__global__ __launch_bounds__(256) void prep_kernel(
    const float* __restrict__ X, const float* __restrict__ W,
    const float* __restrict__ y0)
{
    size_t tid = (size_t)blockIdx.x * blockDim.x + threadIdx.x;
    size_t nthr = (size_t)gridDim.x * blockDim.x;
    if (tid == 0) g_bar = 0u;

    for (size_t i = tid; i < 33554432 / 4; i += nthr) {
        float4 v = ((const float4*)X)[i];
        v.x = tf32r(v.x); v.y = tf32r(v.y); v.z = tf32r(v.z); v.w = tf32r(v.w);
        ((float4*)g_xr)[i] = v;
    }
    for (size_t i = tid; i < 4194304 / 4; i += nthr) {
        float4 v = ((const float4*)W)[i];   // Wx = rows [0,1024)
        v.x = tf32r(v.x); v.y = tf32r(v.y); v.z = tf32r(v.z); v.w = tf32r(v.w);
        ((float4*)g_wxr)[i] = v;
    }
    for (size_t i = tid; i < (BATCH * HDIM) / 4; i += nthr) {
        float4 v = ((const float4*)y0)[i];
        v.x = tf32r(v.x); v.y = tf32r(v.y); v.z = tf32r(v.z); v.w = tf32r(v.w);
        ((float4*)g_ybuf[1])[i] = v;
    }
}

// ================= Kernel 1: Zx = Xr @ Wxr + b (TF32 mma, BM=128 BN=256) =================
#define ZA_STRIDE 20
#define ZB_STRIDE 264    // 264&31=8 -> B-load bank = 8*tg+8*nt+g, bijective
#define ZA_FLOATS (128 * ZA_STRIDE)          // per buffer
#define ZB_FLOATS (16 * ZB_STRIDE)           // per buffer
#define ZX_SMEM_BYTES ((2 * ZA_FLOATS + 2 * ZB_FLOATS) * 4)   // 54272 B

__global__ __launch_bounds__(256, 1) void zx_gemm_kernel(const float* __restrict__ bias)
{
    extern __shared__ __align__(16) float zsm[];
    float* As = zsm;                          // [2][128*20]
    float* Bs = zsm + 2 * ZA_FLOATS;          // [2][16*264]

    const int bm = blockIdx.y * 128;
    const int bn = blockIdx.x * 256;
    const int tid = threadIdx.x;
    const int wid = tid >> 5, lane = tid & 31;
    const int wm = (wid & 1) * 64;            // warp m offset
    const int wn = (wid >> 1) * 64;           // warp n offset (64-wide)
    const int g = lane >> 2, tg = lane & 3;
    const int t4 = lane >> 3, lr = lane & 7;
    const int rowb = wm + 8 * (t4 & 1) + lr;
    const int kadd = 4 * (t4 >> 1);

    float acc[4][8][4];
#pragma unroll
    for (int a = 0; a < 4; a++)
#pragma unroll
        for (int b = 0; b < 8; b++)
#pragma unroll
            for (int i = 0; i < 4; i++) acc[a][b][i] = 0.0f;

    // tile loader: A = 512 16B units (2/thread), B = 1024 units (4/thread)
    auto load_tiles = [&](int buf, int k0) {
#pragma unroll
        for (int h = 0; h < 2; h++) {
            int u = tid + h * 256;
            int row = u >> 2, q = u & 3;
            cp16((unsigned)__cvta_generic_to_shared(
                     &As[buf * ZA_FLOATS + row * ZA_STRIDE + q * 4]),
                 g_xr + (size_t)(bm + row) * NIN + k0 + q * 4);
        }
#pragma unroll
        for (int h = 0; h < 4; h++) {
            int u = tid + h * 256;
            int k = u >> 6, qq = u & 63;      // 64 units per B row
            cp16((unsigned)__cvta_generic_to_shared(
                     &Bs[buf * ZB_FLOATS + k * ZB_STRIDE + qq * 4]),
                 g_wxr + (size_t)(k0 + k) * G4 + bn + qq * 4);
        }
        cp_commit();
    };

    load_tiles(0, 0);

    for (int kb = 0; kb < NIN / 16; kb++) {
        const int cur = kb & 1;
        cp_wait0();
        __syncthreads();
        if (kb < NIN / 16 - 1) load_tiles(cur ^ 1, (kb + 1) * 16);

        const float* A_ = As + cur * ZA_FLOATS;
        const float* B_ = Bs + cur * ZB_FLOATS;
#pragma unroll
        for (int kt = 0; kt < 2; kt++) {
            uint32_t a[4][4];
#pragma unroll
            for (int mt = 0; mt < 4; mt++)
                ldsm4(a[mt], &A_[(rowb + mt * 16) * ZA_STRIDE + kt * 8 + kadd]);
            uint32_t b[8][2];
#pragma unroll
            for (int nt = 0; nt < 8; nt++) {
                b[nt][0] = __float_as_uint(B_[(kt * 8 + tg) * ZB_STRIDE + wn + nt * 8 + g]);
                b[nt][1] = __float_as_uint(B_[(kt * 8 + tg + 4) * ZB_STRIDE + wn + nt * 8 + g]);
            }
#pragma unroll
            for (int mt = 0; mt < 4; mt++)
#pragma unroll
                for (int nt = 0; nt < 8; nt++)
                    mma_tf32(acc[mt][nt], a[mt], b[nt]);
        }
        __syncthreads();
    }

    // epilogue: add bias, store PERMUTED: g_zx[(t*128+blk)*2048 + b*32 + col]
#pragma unroll
    for (int mt = 0; mt < 4; mt++) {
#pragma unroll
        for (int nt = 0; nt < 8; nt++) {
            int n = bn + wn + nt * 8 + 2 * tg;     // even global gate col
            float2 bb = *(const float2*)&bias[n];
            int m0 = bm + wm + mt * 16 + g;        // rows m0, m0+8 (same t)
            int tt = m0 >> 6;
            int blkL = (n & 1023) >> 3;
            int col = ((n >> 10) << 3) + (n & 7);
            size_t base = ((size_t)tt * GRID_R + blkL) * 2048 + (m0 & 63) * 32 + col;
            float2 v0 = make_float2(acc[mt][nt][0] + bb.x, acc[mt][nt][1] + bb.y);
            float2 v1 = make_float2(acc[mt][nt][2] + bb.x, acc[mt][nt][3] + bb.y);
            *(float2*)&g_zx[base] = v0;
            *(float2*)&g_zx[base + 8 * 32] = v1;
        }
    }
}

// ================= Kernel 2: persistent recurrence (TF32 mma, full K-split) =================
#define SM_YS 32768
#define SM_ZS (32768 + 2 * (BATCH * YS_STRIDE))
#define SM_CS (SM_ZS + BATCH * 32)
#define SMEM_FLOATS (SM_CS + BATCH * HPB)
#define SMEM_BYTES (SMEM_FLOATS * 4)

__device__ __forceinline__ void load_y_chunk(int tid, float* dst, const float* src) {
#pragma unroll
    for (int gq = 0; gq < 16; gq++) {
        int grp = tid + gq * THR_R;       // 0..2047
        int b = grp >> 5, q = grp & 31;
        unsigned sa = (unsigned)__cvta_generic_to_shared(dst + b * YS_STRIDE + q * 4);
        cp16(sa, src + b * HDIM + q * 4);
    }
    cp_commit();
}

__global__ __launch_bounds__(THR_R, 1) void lstm_kernel(
    const float* __restrict__ W,      // (2048, 4096); Wh = rows [1024, 2048)
    const float* __restrict__ c0,
    const float* __restrict__ Igate,  // (T, B)
    float* __restrict__ out)
{
    extern __shared__ float smem[];
    float* whs = smem;            // 32768 floats: fragment-layout tf32 Wh^T
    float* ys  = smem + SM_YS;    // double-buffered y chunks; reused as stage
    float* zs  = smem + SM_ZS;    // z tile [64][32] (zx preloaded, reduced acc added)
    float* cs  = smem + SM_CS;    // c state [64][8]

    const int tid = threadIdx.x;
    const int blk = blockIdx.x;
    const int w = tid >> 5, lane = tid & 31;   // warp w owns k-iters w*4..w*4+3 per chunk
    const int g = lane >> 2, tg = lane & 3;

    // ---- one-time: Wh^T fragment layout (tf32-rounded) ----
    const float* WhG = W + (size_t)NIN * G4;
    for (int idx = tid; idx < NIN * 32; idx += THR_R) {
        int i = idx & 3;
        int ln = (idx >> 2) & 31;
        int mt = (idx >> 7) & 1;
        int kt = idx >> 8;
        int gg = ln >> 2, tg2 = ln & 3;
        int k = 8 * kt + tg2 + 4 * (i >> 1);
        int gcol = (2 * mt + (i & 1)) * HDIM + blk * HPB + gg;
        whs[idx] = tf32r(WhG[(size_t)k * G4 + gcol]);
    }
    for (int p = tid; p < BATCH * HPB; p += THR_R)
        cs[p] = c0[(p >> 3) * HDIM + blk * HPB + (p & 7)];
    __syncthreads();

    float* Yout  = out;
    float* Cout  = out + (size_t)T_STEPS * BATCH * HDIM;
    float* cTout = Cout + (size_t)T_STEPS * BATCH * HDIM;

    // reducer constants (thread -> m = lane)
    const int r_m  = lane;
    const int r_g  = lane & 7;
    const int r_h  = (lane >> 3) & 1;
    const int r_mt = lane >> 4;
    const int r_swz = (r_h << 3) | (r_mt << 4);
    const int r_lbase = (4 * r_g) ^ r_swz;     // tg bits (0..1) disjoint, OR'd in later

    // prefetch zx slice for t=0
    {
        const float* zsrc = g_zx + (size_t)blk * 2048;
#pragma unroll
        for (int q = 0; q < 4; q++) {
            int u = tid + q * THR_R;
            cp16((unsigned)__cvta_generic_to_shared(zs + u * 4), zsrc + u * 4);
        }
        cp_commit();
    }

    for (int t = 0; t < T_STEPS; t++) {
        const float* ysrc = g_ybuf[(t & 1) ^ 1];

        // prefetch y chunk 0 (zx(t) already in flight / arrived)
        load_y_chunk(tid, ys, ysrc);

        float acc[2][8][4];
#pragma unroll
        for (int a = 0; a < 2; a++)
#pragma unroll
            for (int b = 0; b < 8; b++)
#pragma unroll
                for (int i = 0; i < 4; i++) acc[a][b][i] = 0.0f;

        cp_wait0();            // zx(t) + y chunk 0
        __syncthreads();

        // ---- z^T += Wh^T @ y^T; warp w owns k-iters w*4..w*4+3 of each chunk ----
        for (int ch = 0; ch < HDIM / KC; ch++) {
            if (ch < HDIM / KC - 1)
                load_y_chunk(tid, ys + ((ch + 1) & 1) * (BATCH * YS_STRIDE),
                             ysrc + (ch + 1) * KC);

            const float* yb = ys + (ch & 1) * (BATCH * YS_STRIDE);
#pragma unroll
            for (int q = 0; q < 4; q++) {
                int ktl = w * 4 + q;
                int ktg = ch * 16 + ktl;
                const float4* wp = ((const float4*)whs) + (size_t)(ktg * 2) * 32 + lane;
                float4 A0 = wp[0];
                float4 A1 = wp[32];
                uint32_t a0[4] = {__float_as_uint(A0.x), __float_as_uint(A0.y),
                                  __float_as_uint(A0.z), __float_as_uint(A0.w)};
                uint32_t a1[4] = {__float_as_uint(A1.x), __float_as_uint(A1.y),
                                  __float_as_uint(A1.z), __float_as_uint(A1.w)};
                int krow = ktl * 8 + tg;
                uint32_t bf[8][2];
#pragma unroll
                for (int nt = 0; nt < 8; nt++) {
                    bf[nt][0] = __float_as_uint(yb[(8 * nt + g) * YS_STRIDE + krow]);
                    bf[nt][1] = __float_as_uint(yb[(8 * nt + g) * YS_STRIDE + krow + 4]);
                }
#pragma unroll
                for (int nt = 0; nt < 8; nt++) {
                    mma_tf32(acc[0][nt], a0, bf[nt]);
                    mma_tf32(acc[1][nt], a1, bf[nt]);
                }
            }
            if (ch < HDIM / KC - 1) cp_wait0();
            __syncthreads();
        }

        // ---- stage 4 partial z tiles (swizzled, conflict-free) ----
        float* stage = ys;   // idle now; 4 * 2048 floats
        {
            float* sp = stage + w * STAGE_P;
#pragma unroll
            for (int mt = 0; mt < 2; mt++)
#pragma unroll
                for (int nt = 0; nt < 8; nt++)
#pragma unroll
                    for (int i = 0; i < 4; i++) {
                        int e = mt * 32 + nt * 4 + i;
                        int sl = lane ^ ((((e >> 1) & 1) << 3) | ((e >> 5) << 4));
                        sp[e * 32 + sl] = acc[mt][nt][i];
                    }
        }
        __syncthreads();

        // ---- reduce: thread handles m = lane, batches 16w..16w+15 ----
#pragma unroll
        for (int bb = 0; bb < 16; bb++) {
            int b = 16 * w + bb;
            int nt = b >> 3, tg2 = (b >> 1) & 3, j = b & 1;
            int e = r_mt * 32 + nt * 4 + 2 * r_h + j;
            int slot = e * 32 + (r_lbase | tg2);
            float s = stage[slot] + stage[STAGE_P + slot] +
                      stage[2 * STAGE_P + slot] + stage[3 * STAGE_P + slot];
            zs[b * 32 + r_m] += s;
        }
        __syncthreads();

        // ---- elementwise LSTM cell: 512 (b,jj) pairs, 4 per thread ----
        float* ywr = g_ybuf[t & 1];
        float yv[4], cv[4];
#pragma unroll
        for (int q = 0; q < 4; q++) {
            int p = tid + q * THR_R;
            int b = p >> 3, jj = p & 7;
            float z0 = zs[b * 32 + jj];
            float z1 = zs[b * 32 + 8 + jj];
            float z2 = zs[b * 32 + 16 + jj];
            float z3 = zs[b * 32 + 24 + jj];
            float ci = fast_tanh(z0);
            float ig = fast_sig(z1);
            float fg = fast_sig(z2);
            float og = fast_sig(z3);
            float cprev = cs[p];
            float c = fmaf(ci, ig, cprev * fg);
            float y = fast_tanh(c) * og;
            float m = Igate[t * BATCH + b];
            c = m * c + (1.0f - m) * cprev;
            y = m * y;
            cs[p] = c;
            yv[q] = y; cv[q] = c;
            ywr[b * HDIM + blk * HPB + jj] = tf32r(y);  // next-step mma input
        }

        // ---- barrier arrive (flat atomic, proven) ----
        __threadfence();
        __syncthreads();
        if (tid == 0) atomicAdd(&g_bar, 1u);

        // prefetch next step's zx into zs during barrier window (zs reads done)
        if (t + 1 < T_STEPS) {
            const float* zsrc = g_zx + ((size_t)(t + 1) * GRID_R + blk) * 2048;
#pragma unroll
            for (int q = 0; q < 4; q++) {
                int u = tid + q * THR_R;
                cp16((unsigned)__cvta_generic_to_shared(zs + u * 4), zsrc + u * 4);
            }
            cp_commit();
        }

        // output stores hidden between arrive and wait (off critical path)
#pragma unroll
        for (int q = 0; q < 4; q++) {
            int p = tid + q * THR_R;
            int b = p >> 3, jj = p & 7;
            size_t row = (size_t)t * BATCH + b;
            int hcol = blk * HPB + jj;
            Yout[row * HDIM + hcol] = yv[q];
            Cout[row * HDIM + hcol] = cv[q];
        }

        // ---- barrier wait: single thread polls ----
        if (tid == 0) {
            unsigned target = (unsigned)GRID_R * (unsigned)(t + 1);
            volatile unsigned* vb = &g_bar;
            while (*vb < target) { }
            __threadfence();
        }
        __syncthreads();
    }

    // final cell state
#pragma unroll
    for (int q = 0; q < 4; q++) {
        int p = tid + q * THR_R;
        cTout[(p >> 3) * HDIM + blk * HPB + (p & 7)] = cs[p];
    }
}

// ================= host =================
extern "C" void kernel_launch(void* const* d_in, const int* in_sizes, int n_in,
                              void* d_out, int out_size)
{
    (void)in_sizes; (void)n_in; (void)out_size;
    const float* X    = (const float*)d_in[0];
    const float* W    = (const float*)d_in[1];
    const float* bias = (const float*)d_in[2];
    const float* y0   = (const float*)d_in[3];
    const float* c0   = (const float*)d_in[4];
    const float* I    = (const float*)d_in[5];
    float* out = (float*)d_out;

    cudaFuncSetAttribute(lstm_kernel,
                         cudaFuncAttributeMaxDynamicSharedMemorySize, SMEM_BYTES);
    cudaFuncSetAttribute(zx_gemm_kernel,
                         cudaFuncAttributeMaxDynamicSharedMemorySize, ZX_SMEM_BYTES);

    prep_kernel<<<512, 256>>>(X, W, y0);

    dim3 g1(G4 / 256, (T_STEPS * BATCH) / 128);
    zx_gemm_kernel<<<g1, 256, ZX_SMEM_BYTES>>>(bias);

    lstm_kernel<<<GRID_R, THR_R, SMEM_BYTES>>>(W, c0, I, out);
}

// round 16
// speedup vs baseline: 1.1033x; 1.0509x over previous
#include <cuda_runtime.h>
#include <cuda_bf16.h>
#include <cstdint>

#define T_STEPS 512
#define BATCH   64
#define NIN     1024
#define HDIM    1024
#define G4      4096      // 4*H
#define GRID_R  128       // persistent blocks (1 per SM, <=148 -> co-resident)
#define THR_R   128       // 4 warps, full K-split (zero redundant smem reads)
#define HPB     8         // h-columns per block (8*4 gates = 32 gate cols)
#define KC      128       // y k-chunk
#define YS_STRIDE 132     // padded row stride for y smem
#define STAGE_P 2048      // stage stride per warp (floats)

// -------- scratch (device globals: allocation-free rule) --------
// zx permuted: [t][blk][b*32 + col]  (2048 floats per (t,blk))
__device__ float    g_zx[134217728];          // 512 MB
__device__ float    g_xr[33554432];           // tf32-rounded X (128 MB)
__device__ float    g_wxr[4194304];           // tf32-rounded Wx (16 MB)
__device__ float    g_ybuf[3][BATCH * HDIM];  // TRIPLE-buffered y state (tf32-rounded)
__device__ unsigned g_grp[256];               // 8 group counters, 128B apart

// ---------------- small helpers ----------------
__device__ __forceinline__ void cp16(unsigned saddr, const void* gptr) {
    asm volatile("cp.async.cg.shared.global [%0], [%1], 16;\n" :: "r"(saddr), "l"(gptr));
}
__device__ __forceinline__ void cp_commit() { asm volatile("cp.async.commit_group;\n"); }
__device__ __forceinline__ void cp_wait0()  { asm volatile("cp.async.wait_group 0;\n" ::: "memory"); }

__device__ __forceinline__ uint32_t tf32b(float x) {
    uint32_t u; asm("cvt.rna.tf32.f32 %0, %1;" : "=r"(u) : "f"(x)); return u;
}
__device__ __forceinline__ float tf32r(float x) { return __uint_as_float(tf32b(x)); }

__device__ __forceinline__ float fast_sig(float x) {
    float e; asm("ex2.approx.f32 %0, %1;" : "=f"(e) : "f"(-1.4426950408889634f * x));
    float r; asm("rcp.approx.f32 %0, %1;" : "=f"(r) : "f"(1.0f + e));
    return r;
}
__device__ __forceinline__ float fast_tanh(float x) {
    return fmaf(2.0f, fast_sig(2.0f * x), -1.0f);
}

__device__ __forceinline__ unsigned ld_flag(const unsigned* f) {
    unsigned v;
    asm volatile("ld.relaxed.gpu.global.u32 %0, [%1];" : "=r"(v) : "l"(f) : "memory");
    return v;
}
__device__ __forceinline__ void spin_flag(const unsigned* f, unsigned target) {
    unsigned v;
    do {
        asm volatile("ld.relaxed.gpu.global.u32 %0, [%1];" : "=r"(v) : "l"(f) : "memory");
    } while (v < target);
}

__device__ __forceinline__ void mma_tf32(float* d, const uint32_t* a, const uint32_t* b) {
    asm volatile(
        "mma.sync.aligned.m16n8k8.row.col.f32.tf32.tf32.f32 "
        "{%0,%1,%2,%3}, {%4,%5,%6,%7}, {%8,%9}, {%0,%1,%2,%3};"
        : "+f"(d[0]), "+f"(d[1]), "+f"(d[2]), "+f"(d[3])
        : "r"(a[0]), "r"(a[1]), "r"(a[2]), "r"(a[3]), "r"(b[0]), "r"(b[1]));
}
__device__ __forceinline__ void ldsm4(uint32_t* r, const float* p) {
    uint32_t sa = (uint32_t)__cvta_generic_to_shared(p);
    asm volatile("ldmatrix.sync.aligned.m8n8.x4.shared.b16 {%0,%1,%2,%3}, [%4];"
                 : "=r"(r[0]), "=r"(r[1]), "=r"(r[2]), "=r"(r[3]) : "r"(sa));
}

// ================= Kernel 0: prep (flags reset + tf32 pre-round) =================
__global__ __launch_bounds__(256) void prep_kernel(
    const float* __restrict__ X, const float* __restrict__ W,
    const float* __restrict__ y0)
{
    size_t tid = (size_t)blockIdx.x * blockDim.x + threadIdx.x;
    size_t nthr = (size_t)gridDim.x * blockDim.x;
    if (blockIdx.x == 0 && threadIdx.x < 256) g_grp[threadIdx.x] = 0u;

    for (size_t i = tid; i < 33554432 / 4; i += nthr) {
        float4 v = ((const float4*)X)[i];
        v.x = tf32r(v.x); v.y = tf32r(v.y); v.z = tf32r(v.z); v.w = tf32r(v.w);
        ((float4*)g_xr)[i] = v;
    }
    for (size_t i = tid; i < 4194304 / 4; i += nthr) {
        float4 v = ((const float4*)W)[i];   // Wx = rows [0,1024)
        v.x = tf32r(v.x); v.y = tf32r(v.y); v.z = tf32r(v.z); v.w = tf32r(v.w);
        ((float4*)g_wxr)[i] = v;
    }
    // y0 -> buffer 2 (read buffer of step 0: (0+2)%3)
    for (size_t i = tid; i < (BATCH * HDIM) / 4; i += nthr) {
        float4 v = ((const float4*)y0)[i];
        v.x = tf32r(v.x); v.y = tf32r(v.y); v.z = tf32r(v.z); v.w = tf32r(v.w);
        ((float4*)g_ybuf[2])[i] = v;
    }
}

// ================= Kernel 1: Zx = Xr @ Wxr + b (TF32 mma, BM=128 BN=256) =================
#define ZA_STRIDE 20
#define ZB_STRIDE 264    // 264&31=8 -> B-load bank = 8*tg+8*nt+g, bijective
#define ZA_FLOATS (128 * ZA_STRIDE)          // per buffer
#define ZB_FLOATS (16 * ZB_STRIDE)           // per buffer
#define ZX_SMEM_BYTES ((2 * ZA_FLOATS + 2 * ZB_FLOATS) * 4)   // 54272 B

__global__ __launch_bounds__(256, 1) void zx_gemm_kernel(const float* __restrict__ bias)
{
    extern __shared__ __align__(16) float zsm[];
    float* As = zsm;                          // [2][128*20]
    float* Bs = zsm + 2 * ZA_FLOATS;          // [2][16*264]

    const int bm = blockIdx.y * 128;
    const int bn = blockIdx.x * 256;
    const int tid = threadIdx.x;
    const int wid = tid >> 5, lane = tid & 31;
    const int wm = (wid & 1) * 64;            // warp m offset
    const int wn = (wid >> 1) * 64;           // warp n offset (64-wide)
    const int g = lane >> 2, tg = lane & 3;
    const int t4 = lane >> 3, lr = lane & 7;
    const int rowb = wm + 8 * (t4 & 1) + lr;
    const int kadd = 4 * (t4 >> 1);

    float acc[4][8][4];
#pragma unroll
    for (int a = 0; a < 4; a++)
#pragma unroll
        for (int b = 0; b < 8; b++)
#pragma unroll
            for (int i = 0; i < 4; i++) acc[a][b][i] = 0.0f;

    auto load_tiles = [&](int buf, int k0) {
#pragma unroll
        for (int h = 0; h < 2; h++) {
            int u = tid + h * 256;
            int row = u >> 2, q = u & 3;
            cp16((unsigned)__cvta_generic_to_shared(
                     &As[buf * ZA_FLOATS + row * ZA_STRIDE + q * 4]),
                 g_xr + (size_t)(bm + row) * NIN + k0 + q * 4);
        }
#pragma unroll
        for (int h = 0; h < 4; h++) {
            int u = tid + h * 256;
            int k = u >> 6, qq = u & 63;
            cp16((unsigned)__cvta_generic_to_shared(
                     &Bs[buf * ZB_FLOATS + k * ZB_STRIDE + qq * 4]),
                 g_wxr + (size_t)(k0 + k) * G4 + bn + qq * 4);
        }
        cp_commit();
    };

    load_tiles(0, 0);

    for (int kb = 0; kb < NIN / 16; kb++) {
        const int cur = kb & 1;
        cp_wait0();
        __syncthreads();
        if (kb < NIN / 16 - 1) load_tiles(cur ^ 1, (kb + 1) * 16);

        const float* A_ = As + cur * ZA_FLOATS;
        const float* B_ = Bs + cur * ZB_FLOATS;
#pragma unroll
        for (int kt = 0; kt < 2; kt++) {
            uint32_t a[4][4];
#pragma unroll
            for (int mt = 0; mt < 4; mt++)
                ldsm4(a[mt], &A_[(rowb + mt * 16) * ZA_STRIDE + kt * 8 + kadd]);
            uint32_t b[8][2];
#pragma unroll
            for (int nt = 0; nt < 8; nt++) {
                b[nt][0] = __float_as_uint(B_[(kt * 8 + tg) * ZB_STRIDE + wn + nt * 8 + g]);
                b[nt][1] = __float_as_uint(B_[(kt * 8 + tg + 4) * ZB_STRIDE + wn + nt * 8 + g]);
            }
#pragma unroll
            for (int mt = 0; mt < 4; mt++)
#pragma unroll
                for (int nt = 0; nt < 8; nt++)
                    mma_tf32(acc[mt][nt], a[mt], b[nt]);
        }
        __syncthreads();
    }

    // epilogue: add bias, store PERMUTED: g_zx[(t*128+blk)*2048 + b*32 + col]
#pragma unroll
    for (int mt = 0; mt < 4; mt++) {
#pragma unroll
        for (int nt = 0; nt < 8; nt++) {
            int n = bn + wn + nt * 8 + 2 * tg;     // even global gate col
            float2 bb = *(const float2*)&bias[n];
            int m0 = bm + wm + mt * 16 + g;        // rows m0, m0+8 (same t)
            int tt = m0 >> 6;
            int blkL = (n & 1023) >> 3;
            int col = ((n >> 10) << 3) + (n & 7);
            size_t base = ((size_t)tt * GRID_R + blkL) * 2048 + (m0 & 63) * 32 + col;
            float2 v0 = make_float2(acc[mt][nt][0] + bb.x, acc[mt][nt][1] + bb.y);
            float2 v1 = make_float2(acc[mt][nt][2] + bb.x, acc[mt][nt][3] + bb.y);
            *(float2*)&g_zx[base] = v0;
            *(float2*)&g_zx[base + 8 * 32] = v1;
        }
    }
}

// ================= Kernel 2: persistent recurrence (group-flag pipelined sync) =================
#define SM_YS 32768
#define SM_ZS (32768 + 2 * (BATCH * YS_STRIDE))
#define SM_CS (SM_ZS + BATCH * 32)
#define SMEM_FLOATS (SM_CS + BATCH * HPB)
#define SMEM_BYTES (SMEM_FLOATS * 4)

__device__ __forceinline__ void load_y_chunk(int tid, float* dst, const float* src) {
#pragma unroll
    for (int gq = 0; gq < 16; gq++) {
        int grp = tid + gq * THR_R;       // 0..2047
        int b = grp >> 5, q = grp & 31;
        unsigned sa = (unsigned)__cvta_generic_to_shared(dst + b * YS_STRIDE + q * 4);
        cp16(sa, src + b * HDIM + q * 4);
    }
    cp_commit();
}

__global__ __launch_bounds__(THR_R, 1) void lstm_kernel(
    const float* __restrict__ W,      // (2048, 4096); Wh = rows [1024, 2048)
    const float* __restrict__ c0,
    const float* __restrict__ Igate,  // (T, B)
    float* __restrict__ out)
{
    extern __shared__ float smem[];
    float* whs = smem;            // 32768 floats: fragment-layout tf32 Wh^T
    float* ys  = smem + SM_YS;    // double-buffered y chunks; reused as stage
    float* zs  = smem + SM_ZS;    // z tile [64][32] (zx preloaded, reduced acc added)
    float* cs  = smem + SM_CS;    // c state [64][8]

    const int tid = threadIdx.x;
    const int blk = blockIdx.x;
    const int w = tid >> 5, lane = tid & 31;   // warp w owns k-iters w*4..w*4+3 per chunk
    const int g = lane >> 2, tg = lane & 3;

    // ---- one-time: Wh^T fragment layout (tf32-rounded) ----
    const float* WhG = W + (size_t)NIN * G4;
    for (int idx = tid; idx < NIN * 32; idx += THR_R) {
        int i = idx & 3;
        int ln = (idx >> 2) & 31;
        int mt = (idx >> 7) & 1;
        int kt = idx >> 8;
        int gg = ln >> 2, tg2 = ln & 3;
        int k = 8 * kt + tg2 + 4 * (i >> 1);
        int gcol = (2 * mt + (i & 1)) * HDIM + blk * HPB + gg;
        whs[idx] = tf32r(WhG[(size_t)k * G4 + gcol]);
    }
    for (int p = tid; p < BATCH * HPB; p += THR_R)
        cs[p] = c0[(p >> 3) * HDIM + blk * HPB + (p & 7)];
    __syncthreads();

    float* Yout  = out;
    float* Cout  = out + (size_t)T_STEPS * BATCH * HDIM;
    float* cTout = Cout + (size_t)T_STEPS * BATCH * HDIM;

    // reducer constants (thread -> m = lane)
    const int r_m  = lane;
    const int r_g  = lane & 7;
    const int r_h  = (lane >> 3) & 1;
    const int r_mt = lane >> 4;
    const int r_swz = (r_h << 3) | (r_mt << 4);
    const int r_lbase = (4 * r_g) ^ r_swz;     // tg bits (0..1) disjoint, OR'd in later

    unsigned* my_grp = &g_grp[(blk >> 4) * 32];

    // prefetch zx slice for t=0
    {
        const float* zsrc = g_zx + (size_t)blk * 2048;
#pragma unroll
        for (int q = 0; q < 4; q++) {
            int u = tid + q * THR_R;
            cp16((unsigned)__cvta_generic_to_shared(zs + u * 4), zsrc + u * 4);
        }
        cp_commit();
    }

    int rbuf = 2, wbuf = 0;       // read buf (t+2)%3, write buf t%3
    unsigned v0g = 0;             // pre-polled group-0 value for next step

    for (int t = 0; t < T_STEPS; t++) {
        const float* ysrc = g_ybuf[rbuf];
        const unsigned tgt = 16u * (unsigned)t;

        // chunk 0 dependency: group 0 (pre-polled at end of previous step)
        if (t && v0g < tgt) spin_flag(&g_grp[0], tgt);
        load_y_chunk(tid, ys, ysrc);
        unsigned vn = 0xFFFFFFFFu;
        if (t) vn = ld_flag(&g_grp[1 * 32]);   // group 1, consumed at ch=0 boundary

        float acc[2][8][4];
#pragma unroll
        for (int a = 0; a < 2; a++)
#pragma unroll
            for (int b = 0; b < 8; b++)
#pragma unroll
                for (int i = 0; i < 4; i++) acc[a][b][i] = 0.0f;

        cp_wait0();            // zx(t) + y chunk 0
        __syncthreads();

        // ---- z^T += Wh^T @ y^T; warp w owns k-iters w*4..w*4+3 of each chunk ----
        for (int ch = 0; ch < HDIM / KC; ch++) {
            if (ch < HDIM / KC - 1) {
                if (t && vn < tgt) spin_flag(&g_grp[(ch + 1) * 32], tgt);
                load_y_chunk(tid, ys + ((ch + 1) & 1) * (BATCH * YS_STRIDE),
                             ysrc + (ch + 1) * KC);
                if (t && ch < HDIM / KC - 2)
                    vn = ld_flag(&g_grp[(ch + 2) * 32]);   // hidden under chunk compute
            }

            const float* yb = ys + (ch & 1) * (BATCH * YS_STRIDE);
#pragma unroll
            for (int q = 0; q < 4; q++) {
                int ktl = w * 4 + q;
                int ktg = ch * 16 + ktl;
                const float4* wp = ((const float4*)whs) + (size_t)(ktg * 2) * 32 + lane;
                float4 A0 = wp[0];
                float4 A1 = wp[32];
                uint32_t a0[4] = {__float_as_uint(A0.x), __float_as_uint(A0.y),
                                  __float_as_uint(A0.z), __float_as_uint(A0.w)};
                uint32_t a1[4] = {__float_as_uint(A1.x), __float_as_uint(A1.y),
                                  __float_as_uint(A1.z), __float_as_uint(A1.w)};
                int krow = ktl * 8 + tg;
                uint32_t bf[8][2];
#pragma unroll
                for (int nt = 0; nt < 8; nt++) {
                    bf[nt][0] = __float_as_uint(yb[(8 * nt + g) * YS_STRIDE + krow]);
                    bf[nt][1] = __float_as_uint(yb[(8 * nt + g) * YS_STRIDE + krow + 4]);
                }
#pragma unroll
                for (int nt = 0; nt < 8; nt++) {
                    mma_tf32(acc[0][nt], a0, bf[nt]);
                    mma_tf32(acc[1][nt], a1, bf[nt]);
                }
            }
            if (ch < HDIM / KC - 1) cp_wait0();
            __syncthreads();
        }

        // ---- stage 4 partial z tiles (swizzled, conflict-free) ----
        float* stage = ys;   // idle now; 4 * 2048 floats
        {
            float* sp = stage + w * STAGE_P;
#pragma unroll
            for (int mt = 0; mt < 2; mt++)
#pragma unroll
                for (int nt = 0; nt < 8; nt++)
#pragma unroll
                    for (int i = 0; i < 4; i++) {
                        int e = mt * 32 + nt * 4 + i;
                        int sl = lane ^ ((((e >> 1) & 1) << 3) | ((e >> 5) << 4));
                        sp[e * 32 + sl] = acc[mt][nt][i];
                    }
        }
        __syncthreads();

        // ---- reduce: thread handles m = lane, batches 16w..16w+15 ----
#pragma unroll
        for (int bb = 0; bb < 16; bb++) {
            int b = 16 * w + bb;
            int nt = b >> 3, tg2 = (b >> 1) & 3, j = b & 1;
            int e = r_mt * 32 + nt * 4 + 2 * r_h + j;
            int slot = e * 32 + (r_lbase | tg2);
            float s = stage[slot] + stage[STAGE_P + slot] +
                      stage[2 * STAGE_P + slot] + stage[3 * STAGE_P + slot];
            zs[b * 32 + r_m] += s;
        }
        __syncthreads();

        // ---- elementwise LSTM cell: 512 (b,jj) pairs, 4 per thread ----
        float* ywr = g_ybuf[wbuf];
        float yv[4], cv[4];
#pragma unroll
        for (int q = 0; q < 4; q++) {
            int p = tid + q * THR_R;
            int b = p >> 3, jj = p & 7;
            float z0 = zs[b * 32 + jj];
            float z1 = zs[b * 32 + 8 + jj];
            float z2 = zs[b * 32 + 16 + jj];
            float z3 = zs[b * 32 + 24 + jj];
            float ci = fast_tanh(z0);
            float ig = fast_sig(z1);
            float fg = fast_sig(z2);
            float og = fast_sig(z3);
            float cprev = cs[p];
            float c = fmaf(ci, ig, cprev * fg);
            float y = fast_tanh(c) * og;
            float m = Igate[t * BATCH + b];
            c = m * c + (1.0f - m) * cprev;
            y = m * y;
            cs[p] = c;
            yv[q] = y; cv[q] = c;
            ywr[b * HDIM + blk * HPB + jj] = tf32r(y);  // next-step mma input
        }

        // ---- arrive: release y-slice on this block's group counter ----
        __threadfence();
        __syncthreads();
        if (tid == 0) atomicAdd(my_grp, 1u);

        // prefetch next step's zx into zs (zs reads done)
        if (t + 1 < T_STEPS) {
            const float* zsrc = g_zx + ((size_t)(t + 1) * GRID_R + blk) * 2048;
#pragma unroll
            for (int q = 0; q < 4; q++) {
                int u = tid + q * THR_R;
                cp16((unsigned)__cvta_generic_to_shared(zs + u * 4), zsrc + u * 4);
            }
            cp_commit();
        }

        // pre-poll group 0 for the next step (hidden under output stores)
        if (t + 1 < T_STEPS) v0g = ld_flag(&g_grp[0]);

        // output stores (off critical path)
#pragma unroll
        for (int q = 0; q < 4; q++) {
            int p = tid + q * THR_R;
            int b = p >> 3, jj = p & 7;
            size_t row = (size_t)t * BATCH + b;
            int hcol = blk * HPB + jj;
            Yout[row * HDIM + hcol] = yv[q];
            Cout[row * HDIM + hcol] = cv[q];
        }

        // rotate triple buffer
        rbuf = wbuf;
        wbuf = (wbuf == 2) ? 0 : wbuf + 1;
    }

    // final cell state
#pragma unroll
    for (int q = 0; q < 4; q++) {
        int p = tid + q * THR_R;
        cTout[(p >> 3) * HDIM + blk * HPB + (p & 7)] = cs[p];
    }
}

// ================= host =================
extern "C" void kernel_launch(void* const* d_in, const int* in_sizes, int n_in,
                              void* d_out, int out_size)
{
    (void)in_sizes; (void)n_in; (void)out_size;
    const float* X    = (const float*)d_in[0];
    const float* W    = (const float*)d_in[1];
    const float* bias = (const float*)d_in[2];
    const float* y0   = (const float*)d_in[3];
    const float* c0   = (const float*)d_in[4];
    const float* I    = (const float*)d_in[5];
    float* out = (float*)d_out;

    cudaFuncSetAttribute(lstm_kernel,
                         cudaFuncAttributeMaxDynamicSharedMemorySize, SMEM_BYTES);
    cudaFuncSetAttribute(zx_gemm_kernel,
                         cudaFuncAttributeMaxDynamicSharedMemorySize, ZX_SMEM_BYTES);

    prep_kernel<<<512, 256>>>(X, W, y0);

    dim3 g1(G4 / 256, (T_STEPS * BATCH) / 128);
    zx_gemm_kernel<<<g1, 256, ZX_SMEM_BYTES>>>(bias);

    lstm_kernel<<<GRID_R, THR_R, SMEM_BYTES>>>(W, c0, I, out);
}